// round 1
// baseline (speedup 1.0000x reference)
#include <cuda_runtime.h>
#include <math.h>

// Problem constants
#define NPTS   1048576
#define DH     256        // mlp_x hidden
#define R      64         // Tucker rank (all three)
#define NQ     1024
#define HQ     128
#define HC     128
#define CIN    64
#define CORE_ELEMS (R*R*R)   // 262144

// ---------------- scratch (device globals; no allocation allowed) -------------
__device__ float g_up[2][8][HQ];      // partial u sums per (axis, cgroup)
__device__ float g_syp[2][8];         // partial sum(y)
__device__ float g_h[HC];             // core hidden tanh
__device__ __align__(16) float g_w12[R*R];   // s1 outer s2
__device__ float g_T[HC+1][R];        // per-(h,a) dot results (row 128 = bc2)
__device__ float g_w2vc[DH+1];        // w2v[0..255], c at [256]

// ---------------- tanh helpers -------------
// Accurate: tanh(x) = 1 - 2/(exp(2x)+1), via ex2.approx + rcp.approx (~1e-6 abs)
__device__ __forceinline__ float tanh_acc(float x) {
    float e, r;
    asm("ex2.approx.f32 %0, %1;" : "=f"(e) : "f"(x * 2.8853900817779268f));
    asm("rcp.approx.f32 %0, %1;" : "=f"(r) : "f"(e + 1.0f));
    return fmaf(-2.0f, r, 1.0f);
}
// HW tanh (1 MUFU), ~5e-4 max abs err
__device__ __forceinline__ float tanh_hw(float x) {
    float y;
    asm("tanh.approx.f32 %0, %1;" : "=f"(y) : "f"(x));
    return y;
}

// ---------------- K1: quad-axis partial sums + core hidden -------------
// grid: 17 blocks x 256 threads. blocks 0..15: (axis, cgroup); block 16: core hidden.
__global__ void __launch_bounds__(256) k1(
    const float* __restrict__ qx0, const float* __restrict__ qx1,
    const float* __restrict__ eqp,
    const float* __restrict__ Wq01, const float* __restrict__ bq01,
    const float* __restrict__ Wq11, const float* __restrict__ bq11,
    const float* __restrict__ ci,   const float* __restrict__ Wc1,
    const float* __restrict__ bc1)
{
    int b = blockIdx.x;
    int t = threadIdx.x;

    if (b == 16) {
        // core hidden: h[k] = tanh(core_init @ Wc1 + bc1), Wc1 is (64,128) row-major
        if (t < HC) {
            float z = bc1[t];
            #pragma unroll 8
            for (int i = 0; i < CIN; i++) z = fmaf(ci[i], Wc1[i * HC + t], z);
            g_h[t] = tanh_acc(z);
        }
        return;
    }

    int ax = b >> 3, g = b & 7;   // axis, c-group (128 quad points)
    const float* qx = ax ? qx1 : qx0;
    const float* Wq = ax ? Wq11 : Wq01;
    const float* bq = ax ? bq11 : bq01;

    __shared__ float sx[128], sy[128], red[256];

    if (t < 128) {
        float x = qx[g * 128 + t];
        float y = sinf(3.14159265358979323846f * eqp[0] * x);
        sx[t] = x; sy[t] = y;
    }
    __syncthreads();

    int k = t & 127, sub = t >> 7;   // each (k) covered by 2 threads, 64 pts each
    float W = Wq[k], bb = bq[k];
    float acc = 0.f;
    int c0 = sub * 64;
    #pragma unroll 8
    for (int c = 0; c < 64; c++) {
        float z = fmaf(sx[c0 + c], W, bb);
        acc = fmaf(sy[c0 + c], tanh_acc(z), acc);
    }
    red[t] = acc;
    __syncthreads();

    if (t < 128) g_up[ax][g][t] = red[t] + red[t + 128];
    if (t == 128) {
        float s = 0.f;
        for (int c = 0; c < 128; c++) s += sy[c];
        g_syp[ax][g] = s;
    }
}

// ---------------- K1b: s1, s2, w12 = s1 (x) s2 -------------
__global__ void __launch_bounds__(256) k1b(
    const float* __restrict__ Wq02, const float* __restrict__ bq02,
    const float* __restrict__ Wq12, const float* __restrict__ bq12)
{
    __shared__ float su[2][HQ];
    __shared__ float s12[128];   // s1 in [0,64), s2 in [64,128)
    __shared__ float ssy[2];
    int t = threadIdx.x;

    {   // reduce partial u
        int ax = t >> 7, k = t & 127;
        float s = 0.f;
        #pragma unroll
        for (int g = 0; g < 8; g++) s += g_up[ax][g][k];
        su[ax][k] = s;
    }
    if (t < 2) {
        float s = 0.f;
        #pragma unroll
        for (int g = 0; g < 8; g++) s += g_syp[t][g];
        ssy[t] = s;
    }
    __syncthreads();

    if (t < 128) {
        int ax = t >> 6, j = t & 63;
        const float* W2 = ax ? Wq12 : Wq02;   // (128,64) row-major
        const float* b2 = ax ? bq12 : bq02;
        float s = ssy[ax] * b2[j];
        #pragma unroll 8
        for (int k = 0; k < HQ; k++) s = fmaf(su[ax][k], W2[k * R + j], s);
        s12[t] = s;
    }
    __syncthreads();

    for (int i = t; i < R * R; i += 256)
        g_w12[i] = s12[i >> 6] * s12[64 + (i & 63)];
}

// ---------------- K2: T[h][a] = dot(Wc2row(h) chunk a, w12)  (DRAM-bound, 134MB) ----
// grid: (129, 8) x 256 threads. h=128 row is bc2. Each block: 8 a's, 128KB streamed.
__global__ void __launch_bounds__(256) k2(
    const float* __restrict__ Wc2, const float* __restrict__ bc2)
{
    int h = blockIdx.x, ga = blockIdx.y;
    const float* row = (h < HC) ? (Wc2 + (size_t)h * CORE_ELEMS) : bc2;

    __shared__ float4 sw[R * R / 4];     // 16 KB: w12
    __shared__ float sred[8][8];
    int t = threadIdx.x;

    for (int i = t; i < R * R / 4; i += 256)
        sw[i] = ((const float4*)g_w12)[i];
    __syncthreads();

    float acc[8];
    #pragma unroll
    for (int aa = 0; aa < 8; aa++) {
        int a = ga * 8 + aa;
        const float4* p = (const float4*)(row + (size_t)a * (R * R));
        float s = 0.f;
        #pragma unroll
        for (int i = 0; i < 4; i++) {
            float4 c  = p[t + i * 256];
            float4 ww = sw[t + i * 256];
            s = fmaf(c.x, ww.x, fmaf(c.y, ww.y, fmaf(c.z, ww.z, fmaf(c.w, ww.w, s))));
        }
        acc[aa] = s;
    }

    #pragma unroll
    for (int aa = 0; aa < 8; aa++) {
        float s = acc[aa];
        #pragma unroll
        for (int o = 16; o; o >>= 1) s += __shfl_xor_sync(0xffffffffu, s, o);
        if ((t & 31) == 0) sred[aa][t >> 5] = s;
    }
    __syncthreads();
    if (t < 8) {
        float s = 0.f;
        #pragma unroll
        for (int w = 0; w < 8; w++) s += sred[t][w];
        g_T[h][ga * 8 + t] = s;
    }
}

// ---------------- K2b: v = h@T + Trow128;  w2v = Wx2@v;  c = bx2.v -------------
__global__ void __launch_bounds__(256) k2b(
    const float* __restrict__ Wx2, const float* __restrict__ bx2)
{
    __shared__ float v[R];
    int t = threadIdx.x;
    if (t < R) {
        float s = g_T[HC][t];
        #pragma unroll 8
        for (int h = 0; h < HC; h++) s = fmaf(g_h[h], g_T[h][t], s);
        v[t] = s;
    }
    __syncthreads();
    float s = 0.f;
    #pragma unroll 8
    for (int a = 0; a < R; a++) s = fmaf(Wx2[t * R + a], v[a], s);   // Wx2 (256,64) rm
    g_w2vc[t] = s;
    if (t == 0) {
        float c = 0.f;
        for (int a = 0; a < R; a++) c = fmaf(bx2[a], v[a], c);
        g_w2vc[DH] = c;
    }
}

// ---------------- K3: main N-point loop (MUFU-bound) -------------
// out[i] = sum_h tanh(x0*W0[h] + x1*W1[h] + b[h]) * w2v[h] + c
#define PPT 8
__global__ void __launch_bounds__(256) k3(
    const float2* __restrict__ inp,
    const float* __restrict__ Wx1, const float* __restrict__ bx1,
    float* __restrict__ out, int n)
{
    __shared__ float4 sw[DH];    // {W0, W1, b, w2v} per hidden unit
    int t = threadIdx.x;
    sw[t] = make_float4(Wx1[t], Wx1[DH + t], bx1[t], g_w2vc[t]);
    float cc = g_w2vc[DH];
    __syncthreads();

    int base = blockIdx.x * (256 * PPT) + t;

    float x0[PPT], x1[PPT], acc[PPT];
    #pragma unroll
    for (int p = 0; p < PPT; p++) {
        int idx = base + p * 256;
        float2 xy = (idx < n) ? inp[idx] : make_float2(0.f, 0.f);
        x0[p] = xy.x; x1[p] = xy.y; acc[p] = 0.f;
    }

    #pragma unroll 4
    for (int h = 0; h < DH; h++) {
        float4 w = sw[h];
        #pragma unroll
        for (int p = 0; p < PPT; p++) {
            float z = fmaf(x0[p], w.x, fmaf(x1[p], w.y, w.z));
            acc[p] = fmaf(tanh_hw(z), w.w, acc[p]);
        }
    }

    #pragma unroll
    for (int p = 0; p < PPT; p++) {
        int idx = base + p * 256;
        if (idx < n) out[idx] = acc[p] + cc;
    }
}

// ---------------- launch -------------
extern "C" void kernel_launch(void* const* d_in, const int* in_sizes, int n_in,
                              void* d_out, int out_size)
{
    const float* input  = (const float*)d_in[0];
    const float* eqp    = (const float*)d_in[1];
    const float* qx0    = (const float*)d_in[2];
    const float* qx1    = (const float*)d_in[3];
    const float* ci     = (const float*)d_in[4];
    const float* Wx1    = (const float*)d_in[5];
    const float* bx1    = (const float*)d_in[6];
    const float* Wx2    = (const float*)d_in[7];
    const float* bx2    = (const float*)d_in[8];
    const float* Wq01   = (const float*)d_in[9];
    const float* bq01   = (const float*)d_in[10];
    const float* Wq02   = (const float*)d_in[11];
    const float* bq02   = (const float*)d_in[12];
    const float* Wq11   = (const float*)d_in[13];
    const float* bq11   = (const float*)d_in[14];
    const float* Wq12   = (const float*)d_in[15];
    const float* bq12   = (const float*)d_in[16];
    const float* Wc1    = (const float*)d_in[17];
    const float* bc1    = (const float*)d_in[18];
    const float* Wc2    = (const float*)d_in[19];
    const float* bc2    = (const float*)d_in[20];

    int n = in_sizes[0] / 2;   // number of collocation points

    k1 <<<17, 256>>>(qx0, qx1, eqp, Wq01, bq01, Wq11, bq11, ci, Wc1, bc1);
    k1b<<<1, 256>>>(Wq02, bq02, Wq12, bq12);
    k2 <<<dim3(129, 8), 256>>>(Wc2, bc2);
    k2b<<<1, 256>>>(Wx2, bx2);

    int blocks = (n + 256 * PPT - 1) / (256 * PPT);
    k3 <<<blocks, 256>>>((const float2*)input, Wx1, bx1, (float*)d_out, n);
}

// round 2
// speedup vs baseline: 1.0994x; 1.0994x over previous
#include <cuda_runtime.h>
#include <math.h>

// Problem constants
#define NPTS   1048576
#define DH     256        // mlp_x hidden
#define R      64         // Tucker rank (all three)
#define NQ     1024
#define HQ     128
#define HC     128
#define CIN    64
#define CORE_ELEMS (R*R*R)   // 262144

// ---------------- scratch (device globals) -------------
__device__ float g_up[2][8][HQ];      // partial u sums per (axis, cgroup)
__device__ float g_syp[2][8];         // partial sum(y)
__device__ float g_h[HC];             // core hidden tanh
__device__ float g_v[R];              // final Tucker-contracted vector (atomic acc)

// ---------------- tanh helpers -------------
__device__ __forceinline__ float tanh_acc(float x) {
    float e, r;
    asm("ex2.approx.f32 %0, %1;" : "=f"(e) : "f"(x * 2.8853900817779268f));
    asm("rcp.approx.f32 %0, %1;" : "=f"(r) : "f"(e + 1.0f));
    return fmaf(-2.0f, r, 1.0f);
}
__device__ __forceinline__ float tanh_hw(float x) {
    float y;
    asm("tanh.approx.f32 %0, %1;" : "=f"(y) : "f"(x));
    return y;
}

// ---------------- K1: quad-axis partial sums + core hidden + zero g_v -------------
// grid: 17 blocks x 256 threads. blocks 0..15: (axis, cgroup); block 16: core hidden.
__global__ void __launch_bounds__(256) k1(
    const float* __restrict__ qx0, const float* __restrict__ qx1,
    const float* __restrict__ eqp,
    const float* __restrict__ Wq01, const float* __restrict__ bq01,
    const float* __restrict__ Wq11, const float* __restrict__ bq11,
    const float* __restrict__ ci,   const float* __restrict__ Wc1,
    const float* __restrict__ bc1)
{
    int b = blockIdx.x;
    int t = threadIdx.x;

    if (b == 16) {
        if (t < R) g_v[t] = 0.f;                 // reset atomic accumulator each replay
        if (t < HC) {
            float z = bc1[t];
            #pragma unroll 8
            for (int i = 0; i < CIN; i++) z = fmaf(ci[i], Wc1[i * HC + t], z);
            g_h[t] = tanh_acc(z);
        }
        return;
    }

    int ax = b >> 3, g = b & 7;
    const float* qx = ax ? qx1 : qx0;
    const float* Wq = ax ? Wq11 : Wq01;
    const float* bq = ax ? bq11 : bq01;

    __shared__ float sx[128], sy[128], red[256];

    if (t < 128) {
        float x = qx[g * 128 + t];
        float y = sinf(3.14159265358979323846f * eqp[0] * x);
        sx[t] = x; sy[t] = y;
    }
    __syncthreads();

    int k = t & 127, sub = t >> 7;
    float W = Wq[k], bb = bq[k];
    float acc = 0.f;
    int c0 = sub * 64;
    #pragma unroll 8
    for (int c = 0; c < 64; c++) {
        float z = fmaf(sx[c0 + c], W, bb);
        acc = fmaf(sy[c0 + c], tanh_acc(z), acc);
    }
    red[t] = acc;
    __syncthreads();

    if (t < 128) g_up[ax][g][t] = red[t] + red[t + 128];
    if (t == 128) {
        float s = 0.f;
        for (int c = 0; c < 128; c++) s += sy[c];
        g_syp[ax][g] = s;
    }
}

// ---------------- K2: fused (s1,s2,w12 prologue) + T[h][a] dots + weighted atomic v ----
// grid: (129, 8) x 256 threads. h=128 row is bc2 (weight 1.0).
__global__ void __launch_bounds__(256) k2(
    const float* __restrict__ Wc2, const float* __restrict__ bc2,
    const float* __restrict__ Wq02, const float* __restrict__ bq02,
    const float* __restrict__ Wq12, const float* __restrict__ bq12)
{
    __shared__ float su[2][HQ];
    __shared__ float s12[128];
    __shared__ float ssy[2];
    __shared__ __align__(16) float sw[R * R];   // 16 KB: w12
    __shared__ float sred[8][8];

    int t = threadIdx.x;
    int h = blockIdx.x, ga = blockIdx.y;

    // --- prologue: recompute s1, s2, w12 (L2-resident tiny inputs) ---
    {
        int ax = t >> 7, k = t & 127;
        float s = 0.f;
        #pragma unroll
        for (int g = 0; g < 8; g++) s += g_up[ax][g][k];
        su[ax][k] = s;
    }
    if (t < 2) {
        float s = 0.f;
        #pragma unroll
        for (int g = 0; g < 8; g++) s += g_syp[t][g];
        ssy[t] = s;
    }
    __syncthreads();

    if (t < 128) {
        int ax = t >> 6, j = t & 63;
        const float* W2 = ax ? Wq12 : Wq02;   // (128,64) row-major
        const float* b2 = ax ? bq12 : bq02;
        float s = ssy[ax] * b2[j];
        #pragma unroll 8
        for (int k = 0; k < HQ; k++) s = fmaf(su[ax][k], W2[k * R + j], s);
        s12[t] = s;
    }
    __syncthreads();

    for (int i = t; i < R * R; i += 256)
        sw[i] = s12[i >> 6] * s12[64 + (i & 63)];
    __syncthreads();

    // --- main: stream 128KB of Wc2 row h, dot against w12 ---
    const float* row = (h < HC) ? (Wc2 + (size_t)h * CORE_ELEMS) : bc2;
    const float4* sw4 = (const float4*)sw;

    float acc[8];
    #pragma unroll
    for (int aa = 0; aa < 8; aa++) {
        int a = ga * 8 + aa;
        const float4* p = (const float4*)(row + (size_t)a * (R * R));
        float s = 0.f;
        #pragma unroll
        for (int i = 0; i < 4; i++) {
            float4 c  = p[t + i * 256];
            float4 ww = sw4[t + i * 256];
            s = fmaf(c.x, ww.x, fmaf(c.y, ww.y, fmaf(c.z, ww.z, fmaf(c.w, ww.w, s))));
        }
        acc[aa] = s;
    }

    #pragma unroll
    for (int aa = 0; aa < 8; aa++) {
        float s = acc[aa];
        #pragma unroll
        for (int o = 16; o; o >>= 1) s += __shfl_xor_sync(0xffffffffu, s, o);
        if ((t & 31) == 0) sred[aa][t >> 5] = s;
    }
    __syncthreads();
    if (t < 8) {
        float wh = (h < HC) ? g_h[h] : 1.0f;
        float s = 0.f;
        #pragma unroll
        for (int w = 0; w < 8; w++) s += sred[t][w];
        atomicAdd(&g_v[ga * 8 + t], wh * s);
    }
}

// ---------------- K3: per-block w2v preamble + main MUFU loop -------------
// out[i] = sum_h tanh(x0*W0[h] + x1*W1[h] + b[h]) * w2v[h] + c
#define PPT 8
__global__ void __launch_bounds__(256) k3(
    const float2* __restrict__ inp,
    const float* __restrict__ Wx1, const float* __restrict__ bx1,
    const float* __restrict__ Wx2, const float* __restrict__ bx2,
    float* __restrict__ out, int n)
{
    __shared__ float4 sw[DH];            // {W0, W1, b, w2v}
    __shared__ __align__(16) float sv[R];
    int t = threadIdx.x;

    if (t < R) sv[t] = g_v[t];
    __syncthreads();

    // w2v[t] = Wx2[t,:] . v   (Wx2 row-major (256,64)); c = bx2 . v
    float w2v = 0.f, cc = 0.f;
    {
        const float4* wrow = (const float4*)(Wx2 + t * R);
        const float4* brow = (const float4*)bx2;
        const float4* v4   = (const float4*)sv;
        #pragma unroll
        for (int a = 0; a < R / 4; a++) {
            float4 w = wrow[a], b = brow[a], v = v4[a];
            w2v = fmaf(w.x, v.x, fmaf(w.y, v.y, fmaf(w.z, v.z, fmaf(w.w, v.w, w2v))));
            cc  = fmaf(b.x, v.x, fmaf(b.y, v.y, fmaf(b.z, v.z, fmaf(b.w, v.w, cc))));
        }
    }
    sw[t] = make_float4(Wx1[t], Wx1[DH + t], bx1[t], w2v);
    __syncthreads();

    int base = blockIdx.x * (256 * PPT) + t;

    float x0[PPT], x1[PPT], acc[PPT];
    #pragma unroll
    for (int p = 0; p < PPT; p++) {
        int idx = base + p * 256;
        float2 xy = (idx < n) ? inp[idx] : make_float2(0.f, 0.f);
        x0[p] = xy.x; x1[p] = xy.y; acc[p] = 0.f;
    }

    #pragma unroll 4
    for (int h = 0; h < DH; h++) {
        float4 w = sw[h];
        #pragma unroll
        for (int p = 0; p < PPT; p++) {
            float z = fmaf(x0[p], w.x, fmaf(x1[p], w.y, w.z));
            acc[p] = fmaf(tanh_hw(z), w.w, acc[p]);
        }
    }

    #pragma unroll
    for (int p = 0; p < PPT; p++) {
        int idx = base + p * 256;
        if (idx < n) out[idx] = acc[p] + cc;
    }
}

// ---------------- launch -------------
extern "C" void kernel_launch(void* const* d_in, const int* in_sizes, int n_in,
                              void* d_out, int out_size)
{
    const float* input  = (const float*)d_in[0];
    const float* eqp    = (const float*)d_in[1];
    const float* qx0    = (const float*)d_in[2];
    const float* qx1    = (const float*)d_in[3];
    const float* ci     = (const float*)d_in[4];
    const float* Wx1    = (const float*)d_in[5];
    const float* bx1    = (const float*)d_in[6];
    const float* Wx2    = (const float*)d_in[7];
    const float* bx2    = (const float*)d_in[8];
    const float* Wq01   = (const float*)d_in[9];
    const float* bq01   = (const float*)d_in[10];
    const float* Wq02   = (const float*)d_in[11];
    const float* bq02   = (const float*)d_in[12];
    const float* Wq11   = (const float*)d_in[13];
    const float* bq11   = (const float*)d_in[14];
    const float* Wq12   = (const float*)d_in[15];
    const float* bq12   = (const float*)d_in[16];
    const float* Wc1    = (const float*)d_in[17];
    const float* bc1    = (const float*)d_in[18];
    const float* Wc2    = (const float*)d_in[19];
    const float* bc2    = (const float*)d_in[20];

    int n = in_sizes[0] / 2;

    k1 <<<17, 256>>>(qx0, qx1, eqp, Wq01, bq01, Wq11, bq11, ci, Wc1, bc1);
    k2 <<<dim3(129, 8), 256>>>(Wc2, bc2, Wq02, bq02, Wq12, bq12);

    int blocks = (n + 256 * PPT - 1) / (256 * PPT);
    k3 <<<blocks, 256>>>((const float2*)input, Wx1, bx1, Wx2, bx2, (float*)d_out, n);
}